// round 1
// baseline (speedup 1.0000x reference)
#include <cuda_runtime.h>
#include <math.h>

#define B_   4
#define S_   2048
#define D_   1024
#define H_   16
#define HD_  64
#define N3_  3072   // 3 * D_

// Scratch for projected K, Q, V in [B, H, S, hd] layout (static device
// globals: allocation-free per harness rules). 32 MB each.
__device__ float g_k[(size_t)B_ * H_ * S_ * HD_];
__device__ float g_q[(size_t)B_ * H_ * S_ * HD_];
__device__ float g_v[(size_t)B_ * H_ * S_ * HD_];

// ---------------------------------------------------------------------------
// QKV GEMM: [8192, 1024] @ [1024, 3072] with direct scatter into g_k/g_q/g_v.
// 64x64 block tile, 4x4 per-thread microtile, K-step 16.
// ---------------------------------------------------------------------------
__global__ __launch_bounds__(256) void qkv_gemm_kernel(
    const float* __restrict__ x, const float* __restrict__ w)
{
    __shared__ float As[16][64];   // [k][row]
    __shared__ float Bs[16][64];   // [k][col]

    const int tid = threadIdx.x;
    const int tx  = tid & 15;      // 0..15 -> 4 cols each
    const int ty  = tid >> 4;      // 0..15 -> 4 rows each
    const int row0 = blockIdx.y * 64;
    const int col0 = blockIdx.x * 64;

    // load indices
    const int ar = tid >> 2;           // 0..63 (row in tile)
    const int ak = (tid & 3) * 4;      // 0,4,8,12 (k in tile)
    const int bk = tid >> 4;           // 0..15 (k in tile)
    const int bc = (tid & 15) * 4;     // 0..60 (col in tile)

    float acc[4][4] = {};

    for (int k0 = 0; k0 < D_; k0 += 16) {
        float4 av = *(const float4*)&x[(size_t)(row0 + ar) * D_ + k0 + ak];
        As[ak + 0][ar] = av.x;
        As[ak + 1][ar] = av.y;
        As[ak + 2][ar] = av.z;
        As[ak + 3][ar] = av.w;
        float4 bv = *(const float4*)&w[(size_t)(k0 + bk) * N3_ + col0 + bc];
        *(float4*)&Bs[bk][bc] = bv;
        __syncthreads();

        #pragma unroll
        for (int kk = 0; kk < 16; kk++) {
            float4 a4 = *(const float4*)&As[kk][ty * 4];
            float4 b4 = *(const float4*)&Bs[kk][tx * 4];
            float a[4] = {a4.x, a4.y, a4.z, a4.w};
            float b[4] = {b4.x, b4.y, b4.z, b4.w};
            #pragma unroll
            for (int i = 0; i < 4; i++)
                #pragma unroll
                for (int j = 0; j < 4; j++)
                    acc[i][j] += a[i] * b[j];
        }
        __syncthreads();
    }

    // Scatter into [B,H,S,hd]. Chunk order in W is (k, q, v).
    // A 64-wide aligned col tile lies entirely within one (part, head).
    const int cbase  = col0 + tx * 4;
    const int part   = cbase >> 10;          // 0=k, 1=q, 2=v
    const int within = cbase & 1023;
    const int h      = within >> 6;
    const int dbase  = within & 63;
    float* dst = (part == 0) ? g_k : (part == 1) ? g_q : g_v;

    #pragma unroll
    for (int i = 0; i < 4; i++) {
        const int r = row0 + ty * 4 + i;
        const int b = r / S_;
        const int s = r - b * S_;
        float* drow = dst + ((size_t)(b * H_ + h) * S_ + s) * HD_ + dbase;
        #pragma unroll
        for (int j = 0; j < 4; j++)
            drow[j] = acc[i][j];
    }
}

// ---------------------------------------------------------------------------
// Flash attention with ALiBi. One block per (b, h, 64-row Q tile).
// 256 threads: thread (ty,tx) owns rows 4ty..4ty+3, cols 4tx..4tx+3.
// ---------------------------------------------------------------------------
#define ROWP 65   // smem row stride (floats) to avoid bank conflicts

__global__ __launch_bounds__(256) void attn_kernel(float* __restrict__ out)
{
    extern __shared__ float sm[];
    float* Qs  = sm;                    // [64][ROWP]  (seq, d)
    float* Ks  = Qs + 64 * ROWP;        // [64][ROWP]  (key, d)
    float* Vs  = Ks + 64 * ROWP;        // [64][ROWP]  (key, d)
    float* Ps  = Vs + 64 * ROWP;        // [64][ROWP]  (qrow, key)
    float* red = Ps + 64 * ROWP;        // [64][16]

    const int tid = threadIdx.x;
    const int tx  = tid & 15;
    const int ty  = tid >> 4;
    const int qt  = blockIdx.x;         // 0..31
    const int h   = blockIdx.y;         // 0..15
    const int b   = blockIdx.z;         // 0..3
    const int bh  = b * H_ + h;
    const int i0  = qt * 64;

    const float slope     = exp2f(-0.5f * (float)(h + 1));  // 1/(2^8)^((h+1)/16)
    const float inv_scale = 1.0f / 32.0f;                    // 1/sqrt(1024)

    const float* qg = g_q + (size_t)bh * S_ * HD_;
    const float* kg = g_k + (size_t)bh * S_ * HD_;
    const float* vg = g_v + (size_t)bh * S_ * HD_;

    // Load Q tile (64 x 64)
    for (int t = tid; t < 64 * 16; t += 256) {
        const int r  = t >> 4;
        const int c4 = (t & 15) * 4;
        float4 v = *(const float4*)&qg[(size_t)(i0 + r) * HD_ + c4];
        Qs[r * ROWP + c4 + 0] = v.x;
        Qs[r * ROWP + c4 + 1] = v.y;
        Qs[r * ROWP + c4 + 2] = v.z;
        Qs[r * ROWP + c4 + 3] = v.w;
    }

    float m_st[4], l_st[4], acc[4][4];
    #pragma unroll
    for (int i = 0; i < 4; i++) {
        m_st[i] = -INFINITY;
        l_st[i] = 0.0f;
        #pragma unroll
        for (int j = 0; j < 4; j++) acc[i][j] = 0.0f;
    }

    for (int kt = 0; kt < S_ / 64; kt++) {
        const int j0 = kt * 64;
        __syncthreads();  // protect Ks/Vs/Ps from previous iteration / Q load done
        for (int t = tid; t < 64 * 16; t += 256) {
            const int r  = t >> 4;
            const int c4 = (t & 15) * 4;
            float4 kv = *(const float4*)&kg[(size_t)(j0 + r) * HD_ + c4];
            Ks[r * ROWP + c4 + 0] = kv.x;
            Ks[r * ROWP + c4 + 1] = kv.y;
            Ks[r * ROWP + c4 + 2] = kv.z;
            Ks[r * ROWP + c4 + 3] = kv.w;
            float4 vv = *(const float4*)&vg[(size_t)(j0 + r) * HD_ + c4];
            Vs[r * ROWP + c4 + 0] = vv.x;
            Vs[r * ROWP + c4 + 1] = vv.y;
            Vs[r * ROWP + c4 + 2] = vv.z;
            Vs[r * ROWP + c4 + 3] = vv.w;
        }
        __syncthreads();

        // Scores: s[i][j] = q_row . k_row
        float s[4][4] = {};
        #pragma unroll 8
        for (int kk = 0; kk < HD_; kk++) {
            float qr[4], kr[4];
            #pragma unroll
            for (int i = 0; i < 4; i++) qr[i] = Qs[(4 * ty + i) * ROWP + kk];
            #pragma unroll
            for (int j = 0; j < 4; j++) kr[j] = Ks[(4 * tx + j) * ROWP + kk];
            #pragma unroll
            for (int i = 0; i < 4; i++)
                #pragma unroll
                for (int j = 0; j < 4; j++)
                    s[i][j] += qr[i] * kr[j];
        }
        // scale + ALiBi bias m_h * (j - i)
        #pragma unroll
        for (int i = 0; i < 4; i++) {
            const float fi = (float)(i0 + 4 * ty + i);
            #pragma unroll
            for (int j = 0; j < 4; j++) {
                const float fj = (float)(j0 + 4 * tx + j);
                s[i][j] = s[i][j] * inv_scale + slope * (fj - fi);
            }
        }

        // Row max reduction
        #pragma unroll
        for (int i = 0; i < 4; i++) {
            float pm = s[i][0];
            #pragma unroll
            for (int j = 1; j < 4; j++) pm = fmaxf(pm, s[i][j]);
            red[(4 * ty + i) * 16 + tx] = pm;
        }
        __syncthreads();
        float mnew[4];
        #pragma unroll
        for (int i = 0; i < 4; i++) {
            float m = m_st[i];
            #pragma unroll
            for (int t = 0; t < 16; t++) m = fmaxf(m, red[(4 * ty + i) * 16 + t]);
            mnew[i] = m;
        }
        __syncthreads();  // red reuse

        // exp, write P, partial row sums
        #pragma unroll
        for (int i = 0; i < 4; i++) {
            float psum = 0.0f;
            #pragma unroll
            for (int j = 0; j < 4; j++) {
                float p = __expf(s[i][j] - mnew[i]);
                Ps[(4 * ty + i) * ROWP + 4 * tx + j] = p;
                psum += p;
            }
            red[(4 * ty + i) * 16 + tx] = psum;
        }
        __syncthreads();

        // Update running stats, rescale accumulators
        #pragma unroll
        for (int i = 0; i < 4; i++) {
            float rs = 0.0f;
            #pragma unroll
            for (int t = 0; t < 16; t++) rs += red[(4 * ty + i) * 16 + t];
            const float alpha = __expf(m_st[i] - mnew[i]);
            l_st[i] = l_st[i] * alpha + rs;
            m_st[i] = mnew[i];
            #pragma unroll
            for (int j = 0; j < 4; j++) acc[i][j] *= alpha;
        }

        // O += P @ V
        #pragma unroll 8
        for (int kk = 0; kk < 64; kk++) {
            float pr[4], vr[4];
            #pragma unroll
            for (int i = 0; i < 4; i++) pr[i] = Ps[(4 * ty + i) * ROWP + kk];
            #pragma unroll
            for (int j = 0; j < 4; j++) vr[j] = Vs[kk * ROWP + 4 * tx + j];
            #pragma unroll
            for (int i = 0; i < 4; i++)
                #pragma unroll
                for (int j = 0; j < 4; j++)
                    acc[i][j] += pr[i] * vr[j];
        }
    }

    // Epilogue: out[b][s][h*64 + d]
    #pragma unroll
    for (int i = 0; i < 4; i++) {
        const int sgl = i0 + 4 * ty + i;
        const float inv_l = 1.0f / l_st[i];
        float* orow = out + ((size_t)b * S_ + sgl) * D_ + h * HD_ + 4 * tx;
        #pragma unroll
        for (int j = 0; j < 4; j++)
            orow[j] = acc[i][j] * inv_l;
    }
}

// ---------------------------------------------------------------------------
extern "C" void kernel_launch(void* const* d_in, const int* in_sizes, int n_in,
                              void* d_out, int out_size)
{
    const float* x = (const float*)d_in[0];      // [4, 2048, 1024]
    const float* w = (const float*)d_in[1];      // [1024, 3072]
    float* out = (float*)d_out;                  // [4, 2048, 1024]

    (void)in_sizes; (void)n_in; (void)out_size;

    // QKV projection
    dim3 gemm_grid(N3_ / 64, (B_ * S_) / 64);    // (48, 128)
    qkv_gemm_kernel<<<gemm_grid, 256>>>(x, w);

    // Attention
    const int smem_bytes = (4 * 64 * ROWP + 64 * 16) * (int)sizeof(float);
    cudaFuncSetAttribute(attn_kernel,
                         cudaFuncAttributeMaxDynamicSharedMemorySize, smem_bytes);
    dim3 attn_grid(S_ / 64, H_, B_);             // (32, 16, 4)
    attn_kernel<<<attn_grid, 256, smem_bytes>>>(out);
}